// round 1
// baseline (speedup 1.0000x reference)
#include <cuda_runtime.h>
#include <math.h>

#define NN 169      // 13*13 nodes
#define NP 176      // padded rows (8 warps * 22)
#define D  128
#define CHN 8
#define NLAYERS 8
#define RPT 22      // rows per warp

struct Smem {
    float h[NP * D];        // activations, resident across layers
    float buf[NP * D];      // hs / agg scratch
    float wstage[32 * D];   // weight k-chunk staging (16KB)
    float slog[NP];         // attn logits / softmax weights
    float gvec[D];          // pooled g
    float red[256];         // reduction scratch
    float scal[2];          // softmax max / inv-sum
};

__device__ __forceinline__ float gelu_exact(float x) {
    return x * normcdff(x);   // x * Phi(x), matches jax gelu(approximate=False)
}

// acc += A[rows of this warp] @ Wg  (Wg: D x D row-major, staged via ws)
__device__ __forceinline__ void gemm_acc(const float* __restrict__ A,
                                         const float* __restrict__ Wg,
                                         float* ws, float4 (&acc)[RPT],
                                         int w, int l) {
    for (int kc = 0; kc < 4; ++kc) {
        __syncthreads();
        {
            const float4* srcv = (const float4*)(Wg + kc * 32 * D);
            float4* dstv = (float4*)ws;
            int t = (w << 5) + l;
#pragma unroll
            for (int i = 0; i < 4; ++i) dstv[t + (i << 8)] = srcv[t + (i << 8)];
        }
        __syncthreads();
        const float* Ap = A + w * D + kc * 32;
        const float4* wsv = (const float4*)ws;
#pragma unroll 4
        for (int k = 0; k < 32; ++k) {
            float4 wv = wsv[(k << 5) + l];
#pragma unroll
            for (int r = 0; r < RPT; ++r) {
                float a = Ap[r * (8 * D) + k];   // broadcast LDS (all lanes same addr)
                acc[r].x = fmaf(a, wv.x, acc[r].x);
                acc[r].y = fmaf(a, wv.y, acc[r].y);
                acc[r].z = fmaf(a, wv.z, acc[r].z);
                acc[r].w = fmaf(a, wv.w, acc[r].w);
            }
        }
    }
}

extern __shared__ float smem_raw[];

__global__ void __launch_bounds__(256, 1)
hexgnn_kernel(const float* __restrict__ x,
              const float* __restrict__ in_w,  const float* __restrict__ in_b,
              const float* __restrict__ in_g,  const float* __restrict__ in_beta,
              const float* __restrict__ msg_w, const float* __restrict__ upd_w,
              const float* __restrict__ upd_b, const float* __restrict__ ln_g,
              const float* __restrict__ ln_b,
              const float* __restrict__ aq_w,  const float* __restrict__ aq_b,
              const float* __restrict__ pp_w,  const float* __restrict__ pp_b,
              const float* __restrict__ v1_w,  const float* __restrict__ v1_b,
              const float* __restrict__ v2_w,  const float* __restrict__ v2_b,
              const float* __restrict__ tf_w,  const float* __restrict__ tf_b,
              float* __restrict__ out, int B)
{
    Smem* S = (Smem*)smem_raw;
    const int tid = threadIdx.x;
    const int w = tid >> 5, l = tid & 31;
    const int b = blockIdx.x;
    const unsigned FULL = 0xffffffffu;

    // ============ embed: h = LN(gelu(x @ in_w + in_b)) ============
    ((float4*)S->wstage)[tid] = ((const float4*)in_w)[tid];   // 8x128 = 1024 floats
    __syncthreads();
    {
        const float* xb = x + (size_t)b * CHN * NN;
        float4 bb = ((const float4*)in_b)[l];
        float4 gg = ((const float4*)in_g)[l];
        float4 be = ((const float4*)in_beta)[l];
#pragma unroll
        for (int r = 0; r < RPT; ++r) {
            int n = w + (r << 3);
            float xv = 0.f;
            if (n < NN && l < CHN) xv = xb[l * NN + n];
            float4 acc = bb;
#pragma unroll
            for (int c = 0; c < CHN; ++c) {
                float a = __shfl_sync(FULL, xv, c);
                float4 wv = ((const float4*)S->wstage)[(c << 5) + l];
                acc.x = fmaf(a, wv.x, acc.x);
                acc.y = fmaf(a, wv.y, acc.y);
                acc.z = fmaf(a, wv.z, acc.z);
                acc.w = fmaf(a, wv.w, acc.w);
            }
            acc.x = gelu_exact(acc.x); acc.y = gelu_exact(acc.y);
            acc.z = gelu_exact(acc.z); acc.w = gelu_exact(acc.w);
            float s = acc.x + acc.y + acc.z + acc.w;
            float q = acc.x * acc.x + acc.y * acc.y + acc.z * acc.z + acc.w * acc.w;
#pragma unroll
            for (int o = 16; o > 0; o >>= 1) {
                s += __shfl_xor_sync(FULL, s, o);
                q += __shfl_xor_sync(FULL, q, o);
            }
            float mu = s * (1.f / D);
            float var = q * (1.f / D) - mu * mu;
            float rstd = rsqrtf(var + 1e-5f);
            float4 o4;
            o4.x = (acc.x - mu) * rstd * gg.x + be.x;
            o4.y = (acc.y - mu) * rstd * gg.y + be.y;
            o4.z = (acc.z - mu) * rstd * gg.z + be.z;
            o4.w = (acc.w - mu) * rstd * gg.w + be.w;
            if (n >= NN) o4 = make_float4(0.f, 0.f, 0.f, 0.f);
            ((float4*)S->h)[(n << 5) + l] = o4;
        }
    }

    // ============ 8 GNN layers, h resident in SMEM ============
    for (int layer = 0; layer < NLAYERS; ++layer) {
        __syncthreads();
        // --- step 1: hs[n] = (sum of neighbor h)/deg into buf ---
#pragma unroll
        for (int it = 0; it < RPT; ++it) {
            int task = tid + (it << 8);      // 0..5631 = NP*32 float4 slots
            int n = task >> 5, dg = task & 31;
            float4 o4 = make_float4(0.f, 0.f, 0.f, 0.f);
            if (n < NN) {
                int i = n / 13, j = n - i * 13;
                const int di[6] = {1, -1, 0, 0, 1, -1};
                const int dj[6] = {0, 0, 1, -1, -1, 1};
                float cnt = 0.f;
                const float4* h4 = (const float4*)S->h;
#pragma unroll
                for (int e = 0; e < 6; ++e) {
                    int ni = i + di[e], nj = j + dj[e];
                    if (ni >= 0 && ni < 13 && nj >= 0 && nj < 13) {
                        float4 hv = h4[(((ni * 13) + nj) << 5) + dg];
                        o4.x += hv.x; o4.y += hv.y; o4.z += hv.z; o4.w += hv.w;
                        cnt += 1.f;
                    }
                }
                float inv = 1.f / cnt;      // cnt >= 2 always
                o4.x *= inv; o4.y *= inv; o4.z *= inv; o4.w *= inv;
            }
            ((float4*)S->buf)[task] = o4;
        }
        // --- GEMM1: agg = hs @ msg_w[layer]  (row-local, in-place safe) ---
        float4 acc[RPT];
#pragma unroll
        for (int r = 0; r < RPT; ++r) acc[r] = make_float4(0.f, 0.f, 0.f, 0.f);
        gemm_acc(S->buf, msg_w + (size_t)layer * D * D, S->wstage, acc, w, l);
#pragma unroll
        for (int r = 0; r < RPT; ++r)
            ((float4*)S->buf)[((w + (r << 3)) << 5) + l] = acc[r];
        // --- GEMM2: out = h @ U_top + agg @ U_bot ---
#pragma unroll
        for (int r = 0; r < RPT; ++r) acc[r] = make_float4(0.f, 0.f, 0.f, 0.f);
        const float* U = upd_w + (size_t)layer * 2 * D * D;
        gemm_acc(S->h,  U,          S->wstage, acc, w, l);
        gemm_acc(S->buf, U + D * D, S->wstage, acc, w, l);
        // --- epilogue: h = LN(gelu(out + b) + h) ---
        {
            float4 ub = ((const float4*)(upd_b + layer * D))[l];
            float4 gg = ((const float4*)(ln_g + layer * D))[l];
            float4 be = ((const float4*)(ln_b + layer * D))[l];
#pragma unroll
            for (int r = 0; r < RPT; ++r) {
                int n = w + (r << 3);
                float4 hv = ((const float4*)S->h)[(n << 5) + l];
                float4 v;
                v.x = gelu_exact(acc[r].x + ub.x) + hv.x;
                v.y = gelu_exact(acc[r].y + ub.y) + hv.y;
                v.z = gelu_exact(acc[r].z + ub.z) + hv.z;
                v.w = gelu_exact(acc[r].w + ub.w) + hv.w;
                float s = v.x + v.y + v.z + v.w;
                float q = v.x * v.x + v.y * v.y + v.z * v.z + v.w * v.w;
#pragma unroll
                for (int o = 16; o > 0; o >>= 1) {
                    s += __shfl_xor_sync(FULL, s, o);
                    q += __shfl_xor_sync(FULL, q, o);
                }
                float mu = s * (1.f / D);
                float var = q * (1.f / D) - mu * mu;
                float rstd = rsqrtf(var + 1e-5f);
                float4 o4;
                o4.x = (v.x - mu) * rstd * gg.x + be.x;
                o4.y = (v.y - mu) * rstd * gg.y + be.y;
                o4.z = (v.z - mu) * rstd * gg.z + be.z;
                o4.w = (v.w - mu) * rstd * gg.w + be.w;
                if (n >= NN) o4 = make_float4(0.f, 0.f, 0.f, 0.f);
                ((float4*)S->h)[(n << 5) + l] = o4;
            }
        }
    }

    // ============ heads ============
    __syncthreads();
    {
        float4 p4 = ((const float4*)pp_w)[l];
        float4 a4 = ((const float4*)aq_w)[l];
        float pb = pp_b[0], ab = aq_b[0];
#pragma unroll
        for (int r = 0; r < RPT; ++r) {
            int n = w + (r << 3);
            if (n < NN) {
                float4 hv = ((const float4*)S->h)[(n << 5) + l];
                float pd = hv.x * p4.x + hv.y * p4.y + hv.z * p4.z + hv.w * p4.w;
                float ad = hv.x * a4.x + hv.y * a4.y + hv.z * a4.z + hv.w * a4.w;
#pragma unroll
                for (int o = 16; o > 0; o >>= 1) {
                    pd += __shfl_xor_sync(FULL, pd, o);
                    ad += __shfl_xor_sync(FULL, ad, o);
                }
                if (l == 0) {
                    out[(size_t)b * NN + n] = pd + pb;
                    S->slog[n] = ad + ab;
                }
            }
        }
    }
    __syncthreads();
    if (w == 0) {   // softmax stats
        float m = -1e30f;
        for (int n = l; n < NN; n += 32) m = fmaxf(m, S->slog[n]);
#pragma unroll
        for (int o = 16; o > 0; o >>= 1) m = fmaxf(m, __shfl_xor_sync(FULL, m, o));
        float s = 0.f;
        for (int n = l; n < NN; n += 32) s += expf(S->slog[n] - m);
#pragma unroll
        for (int o = 16; o > 0; o >>= 1) s += __shfl_xor_sync(FULL, s, o);
        if (l == 0) { S->scal[0] = m; S->scal[1] = 1.f / s; }
    }
    __syncthreads();
    if (tid < NN) S->slog[tid] = expf(S->slog[tid] - S->scal[0]) * S->scal[1];
    __syncthreads();
    if (tid < D) {   // g = sum_n h[n] * attn[n]
        float gv = 0.f;
        for (int n = 0; n < NN; ++n) gv = fmaf(S->h[n * D + tid], S->slog[n], gv);
        S->gvec[tid] = gv;
    }
    __syncthreads();
    {   // value head stage 1: z_j, j = tid (256 threads)
        float zj = v1_b[tid];
        for (int d = 0; d < D; ++d) zj = fmaf(S->gvec[d], v1_w[d * 256 + tid], zj);
        zj = gelu_exact(zj);
        S->red[tid] = zj * v2_w[tid];
    }
    __syncthreads();
    for (int s = 128; s > 0; s >>= 1) {
        if (tid < s) S->red[tid] += S->red[tid + s];
        __syncthreads();
    }
    if (tid == 0) out[(size_t)B * NN + b] = tanhf(S->red[0] + v2_b[0]);
    if (tid < 4) {
        float tv = tf_b[tid];
        for (int d = 0; d < D; ++d) tv = fmaf(S->gvec[d], tf_w[d * 4 + tid], tv);
        out[(size_t)B * NN + B + (size_t)b * 4 + tid] = tv;
    }
}

extern "C" void kernel_launch(void* const* d_in, const int* in_sizes, int n_in,
                              void* d_out, int out_size) {
    const float* x       = (const float*)d_in[0];
    // d_in[1] = src, d_in[2] = dst : adjacency recomputed inline, unused
    const float* in_w    = (const float*)d_in[3];
    const float* in_b    = (const float*)d_in[4];
    const float* in_g    = (const float*)d_in[5];
    const float* in_beta = (const float*)d_in[6];
    const float* msg_w   = (const float*)d_in[7];
    const float* upd_w   = (const float*)d_in[8];
    const float* upd_b   = (const float*)d_in[9];
    const float* ln_g    = (const float*)d_in[10];
    const float* ln_b    = (const float*)d_in[11];
    const float* aq_w    = (const float*)d_in[12];
    const float* aq_b    = (const float*)d_in[13];
    const float* pp_w    = (const float*)d_in[14];
    const float* pp_b    = (const float*)d_in[15];
    const float* v1_w    = (const float*)d_in[16];
    const float* v1_b    = (const float*)d_in[17];
    const float* v2_w    = (const float*)d_in[18];
    const float* v2_b    = (const float*)d_in[19];
    const float* tf_w    = (const float*)d_in[20];
    const float* tf_b    = (const float*)d_in[21];

    int B = in_sizes[0] / (CHN * NN);
    size_t smem = sizeof(Smem);
    cudaFuncSetAttribute(hexgnn_kernel, cudaFuncAttributeMaxDynamicSharedMemorySize,
                         (int)smem);
    hexgnn_kernel<<<B, 256, smem>>>(x, in_w, in_b, in_g, in_beta, msg_w, upd_w,
                                    upd_b, ln_g, ln_b, aq_w, aq_b, pp_w, pp_b,
                                    v1_w, v1_b, v2_w, v2_b, tf_w, tf_b,
                                    (float*)d_out, B);
}

// round 2
// speedup vs baseline: 1.2218x; 1.2218x over previous
#include <cuda_runtime.h>
#include <math.h>

#define NN 169      // 13*13 nodes
#define NP 176      // padded rows (16 warps * 11)
#define D  128
#define CHN 8
#define NLAYERS 8
#define NT 512      // threads per block
#define NW 16       // warps
#define RPT 11      // rows per warp

struct Smem {
    float h[NP * D];        // activations, resident across layers
    float buf[NP * D];      // hs / agg scratch
    float wstage[32 * D];   // weight k-chunk staging (16KB)
    float slog[NP];         // attn logits / softmax weights
    float gvec[D];          // pooled g
    float red[256];         // reduction scratch
    float scal[2];          // softmax max / inv-sum
};

typedef unsigned long long u64;

__device__ __forceinline__ float gelu_exact(float x) {
    return x * normcdff(x);   // x * Phi(x), matches jax gelu(approximate=False)
}

// acc{01,23}[r] (+)= A[rows of warp] @ Wg, packed f32x2, Wg: D x D row-major
__device__ __forceinline__ void gemm_acc(const float* __restrict__ A,
                                         const float* __restrict__ Wg,
                                         float* ws, u64 (&acc0)[RPT], u64 (&acc1)[RPT],
                                         int w, int l, int tid) {
    for (int kc = 0; kc < 4; ++kc) {
        __syncthreads();
        {   // stage 32x128 weight chunk: 1024 float4 / 512 threads
            const float4* srcv = (const float4*)(Wg + kc * 32 * D);
            float4* dstv = (float4*)ws;
            dstv[tid] = srcv[tid];
            dstv[tid + NT] = srcv[tid + NT];
        }
        __syncthreads();
        const float* Ap = A + w * D + kc * 32;
        const float4* wsv = (const float4*)ws;
#pragma unroll 4
        for (int k = 0; k < 32; ++k) {
            float4 wv = wsv[(k << 5) + l];          // LDS.128, conflict-free
            u64 w01, w23;
            asm("mov.b64 %0, {%1, %2};" : "=l"(w01) : "f"(wv.x), "f"(wv.y));
            asm("mov.b64 %0, {%1, %2};" : "=l"(w23) : "f"(wv.z), "f"(wv.w));
#pragma unroll
            for (int r = 0; r < RPT; ++r) {
                float a = Ap[r * (NW * D) + k];      // broadcast LDS
                u64 a2;
                asm("mov.b64 %0, {%1, %1};" : "=l"(a2) : "f"(a));
                asm("fma.rn.f32x2 %0, %1, %2, %0;" : "+l"(acc0[r]) : "l"(a2), "l"(w01));
                asm("fma.rn.f32x2 %0, %1, %2, %0;" : "+l"(acc1[r]) : "l"(a2), "l"(w23));
            }
        }
    }
}

__device__ __forceinline__ float4 unpack_acc(u64 a01, u64 a23) {
    float4 o;
    asm("mov.b64 {%0, %1}, %2;" : "=f"(o.x), "=f"(o.y) : "l"(a01));
    asm("mov.b64 {%0, %1}, %2;" : "=f"(o.z), "=f"(o.w) : "l"(a23));
    return o;
}

extern __shared__ float smem_raw[];

__global__ void __launch_bounds__(NT, 1)
hexgnn_kernel(const float* __restrict__ x,
              const float* __restrict__ in_w,  const float* __restrict__ in_b,
              const float* __restrict__ in_g,  const float* __restrict__ in_beta,
              const float* __restrict__ msg_w, const float* __restrict__ upd_w,
              const float* __restrict__ upd_b, const float* __restrict__ ln_g,
              const float* __restrict__ ln_b,
              const float* __restrict__ aq_w,  const float* __restrict__ aq_b,
              const float* __restrict__ pp_w,  const float* __restrict__ pp_b,
              const float* __restrict__ v1_w,  const float* __restrict__ v1_b,
              const float* __restrict__ v2_w,  const float* __restrict__ v2_b,
              const float* __restrict__ tf_w,  const float* __restrict__ tf_b,
              float* __restrict__ out, int B)
{
    Smem* S = (Smem*)smem_raw;
    const int tid = threadIdx.x;
    const int w = tid >> 5, l = tid & 31;
    const int b = blockIdx.x;
    const unsigned FULL = 0xffffffffu;

    // ============ embed: h = LN(gelu(x @ in_w + in_b)) ============
    if (tid < 256) ((float4*)S->wstage)[tid] = ((const float4*)in_w)[tid]; // 8x128
    __syncthreads();
    {
        const float* xb = x + (size_t)b * CHN * NN;
        float4 bb = ((const float4*)in_b)[l];
        float4 gg = ((const float4*)in_g)[l];
        float4 be = ((const float4*)in_beta)[l];
#pragma unroll
        for (int r = 0; r < RPT; ++r) {
            int n = w + (r << 4);
            float xv = 0.f;
            if (n < NN && l < CHN) xv = xb[l * NN + n];
            float4 acc = bb;
#pragma unroll
            for (int c = 0; c < CHN; ++c) {
                float a = __shfl_sync(FULL, xv, c);
                float4 wv = ((const float4*)S->wstage)[(c << 5) + l];
                acc.x = fmaf(a, wv.x, acc.x);
                acc.y = fmaf(a, wv.y, acc.y);
                acc.z = fmaf(a, wv.z, acc.z);
                acc.w = fmaf(a, wv.w, acc.w);
            }
            acc.x = gelu_exact(acc.x); acc.y = gelu_exact(acc.y);
            acc.z = gelu_exact(acc.z); acc.w = gelu_exact(acc.w);
            float s = acc.x + acc.y + acc.z + acc.w;
            float q = acc.x * acc.x + acc.y * acc.y + acc.z * acc.z + acc.w * acc.w;
#pragma unroll
            for (int o = 16; o > 0; o >>= 1) {
                s += __shfl_xor_sync(FULL, s, o);
                q += __shfl_xor_sync(FULL, q, o);
            }
            float mu = s * (1.f / D);
            float var = q * (1.f / D) - mu * mu;
            float rstd = rsqrtf(var + 1e-5f);
            float4 o4;
            o4.x = (acc.x - mu) * rstd * gg.x + be.x;
            o4.y = (acc.y - mu) * rstd * gg.y + be.y;
            o4.z = (acc.z - mu) * rstd * gg.z + be.z;
            o4.w = (acc.w - mu) * rstd * gg.w + be.w;
            if (n >= NN) o4 = make_float4(0.f, 0.f, 0.f, 0.f);
            ((float4*)S->h)[(n << 5) + l] = o4;
        }
    }

    // ============ 8 GNN layers, h resident in SMEM ============
    for (int layer = 0; layer < NLAYERS; ++layer) {
        __syncthreads();
        // --- step 1: hs[n] = (sum of neighbor h)/deg into buf ---
#pragma unroll
        for (int it = 0; it < RPT; ++it) {
            int task = tid + (it << 9);      // 0..5631 = NP*32 float4 slots
            int n = task >> 5, dg = task & 31;
            float4 o4 = make_float4(0.f, 0.f, 0.f, 0.f);
            if (n < NN) {
                int i = n / 13, j = n - i * 13;
                const int di[6] = {1, -1, 0, 0, 1, -1};
                const int dj[6] = {0, 0, 1, -1, -1, 1};
                float cnt = 0.f;
                const float4* h4 = (const float4*)S->h;
#pragma unroll
                for (int e = 0; e < 6; ++e) {
                    int ni = i + di[e], nj = j + dj[e];
                    if (ni >= 0 && ni < 13 && nj >= 0 && nj < 13) {
                        float4 hv = h4[(((ni * 13) + nj) << 5) + dg];
                        o4.x += hv.x; o4.y += hv.y; o4.z += hv.z; o4.w += hv.w;
                        cnt += 1.f;
                    }
                }
                float inv = 1.f / cnt;      // cnt >= 2 always
                o4.x *= inv; o4.y *= inv; o4.z *= inv; o4.w *= inv;
            }
            ((float4*)S->buf)[task] = o4;
        }
        // --- GEMM1: agg = hs @ msg_w[layer]  (warp-row-local, in-place safe) ---
        u64 acc0[RPT], acc1[RPT];
#pragma unroll
        for (int r = 0; r < RPT; ++r) { acc0[r] = 0ull; acc1[r] = 0ull; }
        gemm_acc(S->buf, msg_w + (size_t)layer * D * D, S->wstage, acc0, acc1, w, l, tid);
#pragma unroll
        for (int r = 0; r < RPT; ++r)
            ((float4*)S->buf)[((w + (r << 4)) << 5) + l] = unpack_acc(acc0[r], acc1[r]);
        // --- GEMM2: out = h @ U_top + agg @ U_bot ---
#pragma unroll
        for (int r = 0; r < RPT; ++r) { acc0[r] = 0ull; acc1[r] = 0ull; }
        const float* U = upd_w + (size_t)layer * 2 * D * D;
        gemm_acc(S->h,   U,         S->wstage, acc0, acc1, w, l, tid);
        gemm_acc(S->buf, U + D * D, S->wstage, acc0, acc1, w, l, tid);
        // --- epilogue: h = LN(gelu(out + b) + h) ---
        {
            float4 ub = ((const float4*)(upd_b + layer * D))[l];
            float4 gg = ((const float4*)(ln_g + layer * D))[l];
            float4 be = ((const float4*)(ln_b + layer * D))[l];
#pragma unroll
            for (int r = 0; r < RPT; ++r) {
                int n = w + (r << 4);
                float4 av = unpack_acc(acc0[r], acc1[r]);
                float4 hv = ((const float4*)S->h)[(n << 5) + l];
                float4 v;
                v.x = gelu_exact(av.x + ub.x) + hv.x;
                v.y = gelu_exact(av.y + ub.y) + hv.y;
                v.z = gelu_exact(av.z + ub.z) + hv.z;
                v.w = gelu_exact(av.w + ub.w) + hv.w;
                float s = v.x + v.y + v.z + v.w;
                float q = v.x * v.x + v.y * v.y + v.z * v.z + v.w * v.w;
#pragma unroll
                for (int o = 16; o > 0; o >>= 1) {
                    s += __shfl_xor_sync(FULL, s, o);
                    q += __shfl_xor_sync(FULL, q, o);
                }
                float mu = s * (1.f / D);
                float var = q * (1.f / D) - mu * mu;
                float rstd = rsqrtf(var + 1e-5f);
                float4 o4;
                o4.x = (v.x - mu) * rstd * gg.x + be.x;
                o4.y = (v.y - mu) * rstd * gg.y + be.y;
                o4.z = (v.z - mu) * rstd * gg.z + be.z;
                o4.w = (v.w - mu) * rstd * gg.w + be.w;
                if (n >= NN) o4 = make_float4(0.f, 0.f, 0.f, 0.f);
                ((float4*)S->h)[(n << 5) + l] = o4;
            }
        }
    }

    // ============ heads ============
    __syncthreads();
    {
        float4 p4 = ((const float4*)pp_w)[l];
        float4 a4 = ((const float4*)aq_w)[l];
        float pb = pp_b[0], ab = aq_b[0];
#pragma unroll
        for (int r = 0; r < RPT; ++r) {
            int n = w + (r << 4);
            if (n < NN) {
                float4 hv = ((const float4*)S->h)[(n << 5) + l];
                float pd = hv.x * p4.x + hv.y * p4.y + hv.z * p4.z + hv.w * p4.w;
                float ad = hv.x * a4.x + hv.y * a4.y + hv.z * a4.z + hv.w * a4.w;
#pragma unroll
                for (int o = 16; o > 0; o >>= 1) {
                    pd += __shfl_xor_sync(FULL, pd, o);
                    ad += __shfl_xor_sync(FULL, ad, o);
                }
                if (l == 0) {
                    out[(size_t)b * NN + n] = pd + pb;
                    S->slog[n] = ad + ab;
                }
            }
        }
    }
    __syncthreads();
    if (w == 0) {   // softmax stats
        float m = -1e30f;
        for (int n = l; n < NN; n += 32) m = fmaxf(m, S->slog[n]);
#pragma unroll
        for (int o = 16; o > 0; o >>= 1) m = fmaxf(m, __shfl_xor_sync(FULL, m, o));
        float s = 0.f;
        for (int n = l; n < NN; n += 32) s += expf(S->slog[n] - m);
#pragma unroll
        for (int o = 16; o > 0; o >>= 1) s += __shfl_xor_sync(FULL, s, o);
        if (l == 0) { S->scal[0] = m; S->scal[1] = 1.f / s; }
    }
    __syncthreads();
    if (tid < NN) S->slog[tid] = expf(S->slog[tid] - S->scal[0]) * S->scal[1];
    __syncthreads();
    if (tid < D) {   // g = sum_n h[n] * attn[n]
        float gv = 0.f;
        for (int n = 0; n < NN; ++n) gv = fmaf(S->h[n * D + tid], S->slog[n], gv);
        S->gvec[tid] = gv;
    }
    __syncthreads();
    if (tid < 256) {   // value head stage 1: z_j, j = tid
        float zj = v1_b[tid];
        for (int d = 0; d < D; ++d) zj = fmaf(S->gvec[d], v1_w[d * 256 + tid], zj);
        zj = gelu_exact(zj);
        S->red[tid] = zj * v2_w[tid];
    }
    __syncthreads();
    for (int s = 128; s > 0; s >>= 1) {
        if (tid < s) S->red[tid] += S->red[tid + s];
        __syncthreads();
    }
    if (tid == 0) out[(size_t)B * NN + b] = tanhf(S->red[0] + v2_b[0]);
    if (tid < 4) {
        float tv = tf_b[tid];
        for (int d = 0; d < D; ++d) tv = fmaf(S->gvec[d], tf_w[d * 4 + tid], tv);
        out[(size_t)B * NN + B + (size_t)b * 4 + tid] = tv;
    }
}

extern "C" void kernel_launch(void* const* d_in, const int* in_sizes, int n_in,
                              void* d_out, int out_size) {
    const float* x       = (const float*)d_in[0];
    // d_in[1] = src, d_in[2] = dst : adjacency recomputed inline, unused
    const float* in_w    = (const float*)d_in[3];
    const float* in_b    = (const float*)d_in[4];
    const float* in_g    = (const float*)d_in[5];
    const float* in_beta = (const float*)d_in[6];
    const float* msg_w   = (const float*)d_in[7];
    const float* upd_w   = (const float*)d_in[8];
    const float* upd_b   = (const float*)d_in[9];
    const float* ln_g    = (const float*)d_in[10];
    const float* ln_b    = (const float*)d_in[11];
    const float* aq_w    = (const float*)d_in[12];
    const float* aq_b    = (const float*)d_in[13];
    const float* pp_w    = (const float*)d_in[14];
    const float* pp_b    = (const float*)d_in[15];
    const float* v1_w    = (const float*)d_in[16];
    const float* v1_b    = (const float*)d_in[17];
    const float* v2_w    = (const float*)d_in[18];
    const float* v2_b    = (const float*)d_in[19];
    const float* tf_w    = (const float*)d_in[20];
    const float* tf_b    = (const float*)d_in[21];

    int B = in_sizes[0] / (CHN * NN);
    size_t smem = sizeof(Smem);
    cudaFuncSetAttribute(hexgnn_kernel, cudaFuncAttributeMaxDynamicSharedMemorySize,
                         (int)smem);
    hexgnn_kernel<<<B, NT, smem>>>(x, in_w, in_b, in_g, in_beta, msg_w, upd_w,
                                   upd_b, ln_g, ln_b, aq_w, aq_b, pp_w, pp_b,
                                   v1_w, v1_b, v2_w, v2_b, tf_w, tf_b,
                                   (float*)d_out, B);
}

// round 15
// speedup vs baseline: 1.3523x; 1.1068x over previous
#include <cuda_runtime.h>
#include <math.h>

#define NN 169        // 13*13 nodes
#define NPAIR 88      // row pairs (rows padded to 176)
#define D 128
#define CHN 8
#define NLAYERS 8
#define NT 512
#define NW 16

typedef unsigned long long u64;

// Packed activation layout: hpk[pair][k] = float2 {row 2p, row 2p+1}, k-major.
// float index = p*256 + 2k + parity.
struct Smem {
    float hpk[NPAIR * 256];      // 88 KB resident activations (packed)
    float apk[NPAIR * 256];      // 88 KB neighbor-sum / msg scratch (packed)
    float wstage[2][32 * D];     // 32 KB double-buffered weight chunks
    float slog[172];
    float gvec[D];
    float red[256];
    float scal[2];
};

__device__ __forceinline__ float gelu_exact(float x) { return x * normcdff(x); }

__device__ __forceinline__ float2 up64(u64 v) {
    float2 r; asm("mov.b64 {%0,%1},%2;" : "=f"(r.x), "=f"(r.y) : "l"(v)); return r;
}
__device__ __forceinline__ u64 pk64(float a, float b) {
    u64 r; asm("mov.b64 %0,{%1,%2};" : "=l"(r) : "f"(a), "f"(b)); return r;
}
__device__ __forceinline__ u64 dup32(float a) {
    u64 r; asm("mov.b64 %0,{%1,%1};" : "=l"(r) : "f"(a)); return r;
}
__device__ __forceinline__ void ffma2(u64& acc, u64 a, u64 w_) {
    asm("fma.rn.f32x2 %0,%1,%2,%0;" : "+l"(acc) : "l"(a), "l"(w_));
}

// acc[r][c] (+)= Apacked @ Wg ; rows {2p,2p+1} in packed halves, p = w + 16r
__device__ __forceinline__ void gemm_acc(const ulonglong2* __restrict__ Au2,
                                         const float* __restrict__ Wg,
                                         float* wsbase, u64 (&acc)[6][4],
                                         int w, int l, int tid) {
    {   // stage chunk 0
        const float4* srcv = (const float4*)Wg;
        float4* dstv = (float4*)wsbase;
        dstv[tid] = srcv[tid];
        dstv[tid + NT] = srcv[tid + NT];
    }
    for (int kc = 0; kc < 4; ++kc) {
        __syncthreads();
        if (kc < 3) {   // prefetch next chunk into alternate buffer
            const float4* srcv = (const float4*)(Wg + (kc + 1) * 32 * D);
            float4* dstv = (float4*)(wsbase + ((kc + 1) & 1) * (32 * D));
            dstv[tid] = srcv[tid];
            dstv[tid + NT] = srcv[tid + NT];
        }
        const float4* wsv = (const float4*)(wsbase + (kc & 1) * (32 * D));
        const ulonglong2* Ab = Au2 + kc * 16;
#pragma unroll 8
        for (int kp = 0; kp < 16; ++kp) {
            float4 w0 = wsv[((2 * kp) << 5) + l];        // W[k0][4l..4l+3]
            float4 w1 = wsv[((2 * kp + 1) << 5) + l];
            u64 wd0[4], wd1[4];
            wd0[0] = dup32(w0.x); wd0[1] = dup32(w0.y);
            wd0[2] = dup32(w0.z); wd0[3] = dup32(w0.w);
            wd1[0] = dup32(w1.x); wd1[1] = dup32(w1.y);
            wd1[2] = dup32(w1.z); wd1[3] = dup32(w1.w);
#pragma unroll
            for (int r = 0; r < 5; ++r) {
                ulonglong2 av = Ab[(w + (r << 4)) * 64 + kp];  // ks {2kp,2kp+1}
                ffma2(acc[r][0], av.x, wd0[0]); ffma2(acc[r][1], av.x, wd0[1]);
                ffma2(acc[r][2], av.x, wd0[2]); ffma2(acc[r][3], av.x, wd0[3]);
                ffma2(acc[r][0], av.y, wd1[0]); ffma2(acc[r][1], av.y, wd1[1]);
                ffma2(acc[r][2], av.y, wd1[2]); ffma2(acc[r][3], av.y, wd1[3]);
            }
            if (w < 8) {   // pair w+80 only exists for warps 0..7 (88 pairs)
                ulonglong2 av = Ab[(w + 80) * 64 + kp];
                ffma2(acc[5][0], av.x, wd0[0]); ffma2(acc[5][1], av.x, wd0[1]);
                ffma2(acc[5][2], av.x, wd0[2]); ffma2(acc[5][3], av.x, wd0[3]);
                ffma2(acc[5][0], av.y, wd1[0]); ffma2(acc[5][1], av.y, wd1[1]);
                ffma2(acc[5][2], av.y, wd1[2]); ffma2(acc[5][3], av.y, wd1[3]);
            }
        }
    }
}

extern __shared__ float smem_raw[];

__global__ void __launch_bounds__(NT, 1)
hexgnn_kernel(const float* __restrict__ x,
              const float* __restrict__ in_w,  const float* __restrict__ in_b,
              const float* __restrict__ in_g,  const float* __restrict__ in_beta,
              const float* __restrict__ msg_w, const float* __restrict__ upd_w,
              const float* __restrict__ upd_b, const float* __restrict__ ln_g,
              const float* __restrict__ ln_b,
              const float* __restrict__ aq_w,  const float* __restrict__ aq_b,
              const float* __restrict__ pp_w,  const float* __restrict__ pp_b,
              const float* __restrict__ v1_w,  const float* __restrict__ v1_b,
              const float* __restrict__ v2_w,  const float* __restrict__ v2_b,
              const float* __restrict__ tf_w,  const float* __restrict__ tf_b,
              float* __restrict__ out, int B)
{
    Smem* S = (Smem*)smem_raw;
    const int tid = threadIdx.x;
    const int w = tid >> 5, l = tid & 31;
    const int b = blockIdx.x;
    const unsigned FULL = 0xffffffffu;
    ulonglong2* hu2 = (ulonglong2*)S->hpk;
    ulonglong2* au2 = (ulonglong2*)S->apk;

    // ============ embed: h = LN(gelu(x @ in_w + in_b)), packed store ============
    if (tid < 256) ((float4*)S->wstage[0])[tid] = ((const float4*)in_w)[tid];
    __syncthreads();
    {
        const float* xb = x + (size_t)b * CHN * NN;
        float4 bb = ((const float4*)in_b)[l];
        float4 gg = ((const float4*)in_g)[l];
        float4 be = ((const float4*)in_beta)[l];
#pragma unroll
        for (int r = 0; r < 11; ++r) {
            int n = w + (r << 4);                     // 0..175
            float xv = 0.f;
            if (n < NN && l < CHN) xv = xb[l * NN + n];
            float4 acc = bb;
#pragma unroll
            for (int c = 0; c < CHN; ++c) {
                float a = __shfl_sync(FULL, xv, c);
                float4 wv = ((const float4*)S->wstage[0])[(c << 5) + l];
                acc.x = fmaf(a, wv.x, acc.x); acc.y = fmaf(a, wv.y, acc.y);
                acc.z = fmaf(a, wv.z, acc.z); acc.w = fmaf(a, wv.w, acc.w);
            }
            acc.x = gelu_exact(acc.x); acc.y = gelu_exact(acc.y);
            acc.z = gelu_exact(acc.z); acc.w = gelu_exact(acc.w);
            float s = acc.x + acc.y + acc.z + acc.w;
            float q = acc.x * acc.x + acc.y * acc.y + acc.z * acc.z + acc.w * acc.w;
#pragma unroll
            for (int o = 16; o > 0; o >>= 1) {
                s += __shfl_xor_sync(FULL, s, o);
                q += __shfl_xor_sync(FULL, q, o);
            }
            float mu = s * (1.f / D);
            float rstd = rsqrtf(q * (1.f / D) - mu * mu + 1e-5f);
            float4 o4;
            o4.x = (acc.x - mu) * rstd * gg.x + be.x;
            o4.y = (acc.y - mu) * rstd * gg.y + be.y;
            o4.z = (acc.z - mu) * rstd * gg.z + be.z;
            o4.w = (acc.w - mu) * rstd * gg.w + be.w;
            if (n >= NN) o4 = make_float4(0.f, 0.f, 0.f, 0.f);
            float* hp = S->hpk + (n >> 1) * 256 + 8 * l + (n & 1);
            hp[0] = o4.x; hp[2] = o4.y; hp[4] = o4.z; hp[6] = o4.w;
        }
    }

    // ============ 8 GNN layers ============
    for (int layer = 0; layer < NLAYERS; ++layer) {
        __syncthreads();
        // --- neighbor mean into apk (packed). Warp owns pairs p = w+16*it ---
        const float4* h4 = (const float4*)S->hpk;
        float4* a4 = (float4*)S->apk;
#pragma unroll
        for (int it = 0; it < 6; ++it) {
            int p = w + (it << 4);
            if (p >= NPAIR) continue;                 // warp-uniform
            int na = 2 * p, nb = na + 1;
            bool av = na < NN, bv = nb < NN;
            int ia = na / 13, ja = na - ia * 13;
            int ib = nb / 13, jb = nb - ib * 13;
            bool vA13  = av && (ia + 1 < 13);
            bool vAm13 = av && (ia - 1 >= 0);
            bool vA1   = av && (ja + 1 < 13);
            bool vAm1  = av && (ja - 1 >= 0);
            bool vA12  = av && (ia + 1 < 13) && (ja - 1 >= 0);
            bool vAm12 = av && (ia - 1 >= 0) && (ja + 1 < 13);
            bool vB13  = bv && (ib + 1 < 13);
            bool vBm13 = bv && (ib - 1 >= 0);
            bool vB1   = bv && (jb + 1 < 13);
            bool vBm1  = bv && (jb - 1 >= 0);
            bool vB12  = bv && (ib + 1 < 13) && (jb - 1 >= 0);
            bool vBm12 = bv && (ib - 1 >= 0) && (jb + 1 < 13);
            float invA = av ? 1.f / (float)(vA13 + vAm13 + vA1 + vAm1 + vA12 + vAm12) : 0.f;
            float invB = bv ? 1.f / (float)(vB13 + vBm13 + vB1 + vBm1 + vB12 + vBm12) : 0.f;
#pragma unroll
            for (int jj = 0; jj < 2; ++jj) {
                int j = l + (jj << 5);                // float4 idx within pair: ks {2j,2j+1}
                float sa0 = 0.f, sa1 = 0.f, sb0 = 0.f, sb1 = 0.f;
                float4 f;
                if (vA13 | vA12 | vB12) {
                    f = h4[(p + 6) * 64 + j];
                    if (vA13) { sa0 += f.y; sa1 += f.w; }
                    if (vA12) { sa0 += f.x; sa1 += f.z; }
                    if (vB12) { sb0 += f.y; sb1 += f.w; }
                }
                if (vAm13) { f = h4[(p - 7) * 64 + j]; sa0 += f.y; sa1 += f.w; }
                if (vA1 | vBm1) {
                    f = h4[p * 64 + j];
                    if (vA1)  { sa0 += f.y; sa1 += f.w; }
                    if (vBm1) { sb0 += f.x; sb1 += f.z; }
                }
                if (vAm1) { f = h4[(p - 1) * 64 + j]; sa0 += f.y; sa1 += f.w; }
                if (vAm12 | vBm13 | vBm12) {
                    f = h4[(p - 6) * 64 + j];
                    if (vAm12) { sa0 += f.x; sa1 += f.z; }
                    if (vBm13) { sb0 += f.x; sb1 += f.z; }
                    if (vBm12) { sb0 += f.y; sb1 += f.w; }
                }
                if (vB1)  { f = h4[(p + 1) * 64 + j]; sb0 += f.x; sb1 += f.z; }
                if (vB13) { f = h4[(p + 7) * 64 + j]; sb0 += f.x; sb1 += f.z; }
                a4[p * 64 + j] = make_float4(sa0 * invA, sb0 * invB, sa1 * invA, sb1 * invB);
            }
        }
        // --- GEMM1: agg = hs @ msg_w, packed in-place (warp-local rows) ---
        u64 acc[6][4];
#pragma unroll
        for (int r = 0; r < 6; ++r)
#pragma unroll
            for (int c = 0; c < 4; ++c) acc[r][c] = 0ull;
        gemm_acc((const ulonglong2*)S->apk, msg_w + (size_t)layer * D * D,
                 &S->wstage[0][0], acc, w, l, tid);
#pragma unroll
        for (int r = 0; r < 6; ++r) {
            int p = w + (r << 4);
            if (p < NPAIR) {
                au2[p * 64 + 2 * l]     = make_ulonglong2(acc[r][0], acc[r][1]);
                au2[p * 64 + 2 * l + 1] = make_ulonglong2(acc[r][2], acc[r][3]);
            }
        }
        // --- GEMM2: out = h @ U_top + agg @ U_bot ---
#pragma unroll
        for (int r = 0; r < 6; ++r)
#pragma unroll
            for (int c = 0; c < 4; ++c) acc[r][c] = 0ull;
        const float* U = upd_w + (size_t)layer * 2 * D * D;
        gemm_acc((const ulonglong2*)S->hpk, U,         &S->wstage[0][0], acc, w, l, tid);
        gemm_acc((const ulonglong2*)S->apk, U + D * D, &S->wstage[0][0], acc, w, l, tid);
        // --- epilogue: h = LN(gelu(out+b) + h), rows packed ---
        {
            float4 ub = ((const float4*)(upd_b + layer * D))[l];
            float4 gg = ((const float4*)(ln_g + layer * D))[l];
            float4 be = ((const float4*)(ln_b + layer * D))[l];
            float ubc[4] = {ub.x, ub.y, ub.z, ub.w};
            float ggc[4] = {gg.x, gg.y, gg.z, gg.w};
            float bec[4] = {be.x, be.y, be.z, be.w};
#pragma unroll
            for (int r = 0; r < 6; ++r) {
                int p = w + (r << 4);
                if (p >= NPAIR) continue;
                int na = 2 * p, nb = na + 1;
                ulonglong2 hA = hu2[p * 64 + 2 * l];
                ulonglong2 hB = hu2[p * 64 + 2 * l + 1];
                u64 hc[4] = {hA.x, hA.y, hB.x, hB.y};
                float vA[4], vB[4];
                float sA = 0.f, qA = 0.f, sB = 0.f, qB = 0.f;
#pragma unroll
                for (int c = 0; c < 4; ++c) {
                    float2 ac = up64(acc[r][c]);
                    float2 hcc = up64(hc[c]);
                    vA[c] = gelu_exact(ac.x + ubc[c]) + hcc.x;
                    vB[c] = gelu_exact(ac.y + ubc[c]) + hcc.y;
                    sA += vA[c]; qA += vA[c] * vA[c];
                    sB += vB[c]; qB += vB[c] * vB[c];
                }
#pragma unroll
                for (int o = 16; o > 0; o >>= 1) {
                    sA += __shfl_xor_sync(FULL, sA, o);
                    qA += __shfl_xor_sync(FULL, qA, o);
                    sB += __shfl_xor_sync(FULL, sB, o);
                    qB += __shfl_xor_sync(FULL, qB, o);
                }
                float muA = sA * (1.f / D);
                float rsA = rsqrtf(qA * (1.f / D) - muA * muA + 1e-5f);
                float muB = sB * (1.f / D);
                float rsB = rsqrtf(qB * (1.f / D) - muB * muB + 1e-5f);
                float oA[4], oB[4];
                bool avv = na < NN, bvv = nb < NN;
#pragma unroll
                for (int c = 0; c < 4; ++c) {
                    oA[c] = avv ? (vA[c] - muA) * rsA * ggc[c] + bec[c] : 0.f;
                    oB[c] = bvv ? (vB[c] - muB) * rsB * ggc[c] + bec[c] : 0.f;
                }
                hu2[p * 64 + 2 * l]     = make_ulonglong2(pk64(oA[0], oB[0]), pk64(oA[1], oB[1]));
                hu2[p * 64 + 2 * l + 1] = make_ulonglong2(pk64(oA[2], oB[2]), pk64(oA[3], oB[3]));
            }
        }
    }

    // ============ heads ============
    __syncthreads();
    {
        float4 p4 = ((const float4*)pp_w)[l];
        float4 a4h = ((const float4*)aq_w)[l];
        float pc[4] = {p4.x, p4.y, p4.z, p4.w};
        float ac4[4] = {a4h.x, a4h.y, a4h.z, a4h.w};
        float pb = pp_b[0], ab = aq_b[0];
#pragma unroll
        for (int it = 0; it < 6; ++it) {
            int p = w + (it << 4);
            if (p >= NPAIR) continue;
            int na = 2 * p, nb = na + 1;
            ulonglong2 hA = hu2[p * 64 + 2 * l];
            ulonglong2 hB = hu2[p * 64 + 2 * l + 1];
            u64 hc[4] = {hA.x, hA.y, hB.x, hB.y};
            float pdA = 0.f, adA = 0.f, pdB = 0.f, adB = 0.f;
#pragma unroll
            for (int c = 0; c < 4; ++c) {
                float2 hv = up64(hc[c]);
                pdA = fmaf(hv.x, pc[c], pdA); adA = fmaf(hv.x, ac4[c], adA);
                pdB = fmaf(hv.y, pc[c], pdB); adB = fmaf(hv.y, ac4[c], adB);
            }
#pragma unroll
            for (int o = 16; o > 0; o >>= 1) {
                pdA += __shfl_xor_sync(FULL, pdA, o);
                adA += __shfl_xor_sync(FULL, adA, o);
                pdB += __shfl_xor_sync(FULL, pdB, o);
                adB += __shfl_xor_sync(FULL, adB, o);
            }
            if (l == 0) {
                if (na < NN) { out[(size_t)b * NN + na] = pdA + pb; S->slog[na] = adA + ab; }
                if (nb < NN) { out[(size_t)b * NN + nb] = pdB + pb; S->slog[nb] = adB + ab; }
            }
        }
    }
    __syncthreads();
    if (w == 0) {
        float m = -1e30f;
        for (int n = l; n < NN; n += 32) m = fmaxf(m, S->slog[n]);
#pragma unroll
        for (int o = 16; o > 0; o >>= 1) m = fmaxf(m, __shfl_xor_sync(FULL, m, o));
        float s = 0.f;
        for (int n = l; n < NN; n += 32) s += expf(S->slog[n] - m);
#pragma unroll
        for (int o = 16; o > 0; o >>= 1) s += __shfl_xor_sync(FULL, s, o);
        if (l == 0) { S->scal[0] = m; S->scal[1] = 1.f / s; }
    }
    __syncthreads();
    if (tid < NN) S->slog[tid] = expf(S->slog[tid] - S->scal[0]) * S->scal[1];
    __syncthreads();
    if (tid < D) {
        float gv = 0.f;
        const float2* h2 = (const float2*)S->hpk;
        for (int p = 0; p < 84; ++p) {
            float2 f = h2[p * 128 + tid];
            gv = fmaf(f.x, S->slog[2 * p], gv);
            gv = fmaf(f.y, S->slog[2 * p + 1], gv);
        }
        gv = fmaf(h2[84 * 128 + tid].x, S->slog[168], gv);   // row 168 only
        S->gvec[tid] = gv;
    }
    __syncthreads();
    if (tid < 256) {
        float zj = v1_b[tid];
        for (int d = 0; d < D; ++d) zj = fmaf(S->gvec[d], v1_w[d * 256 + tid], zj);
        S->red[tid] = gelu_exact(zj) * v2_w[tid];
    }
    __syncthreads();
    for (int s = 128; s > 0; s >>= 1) {
        if (tid < s) S->red[tid] += S->red[tid + s];
        __syncthreads();
    }
    if (tid == 0) out[(size_t)B * NN + b] = tanhf(S->red[0] + v2_b[0]);
    if (tid < 4) {
        float tv = tf_b[tid];
        for (int d = 0; d < D; ++d) tv = fmaf(S->gvec[d], tf_w[d * 4 + tid], tv);
        out[(size_t)B * NN + B + (size_t)b * 4 + tid] = tv;
    }
}

extern "C" void kernel_launch(void* const* d_in, const int* in_sizes, int n_in,
                              void* d_out, int out_size) {
    const float* x       = (const float*)d_in[0];
    const float* in_w    = (const float*)d_in[3];
    const float* in_b    = (const float*)d_in[4];
    const float* in_g    = (const float*)d_in[5];
    const float* in_beta = (const float*)d_in[6];
    const float* msg_w   = (const float*)d_in[7];
    const float* upd_w   = (const float*)d_in[8];
    const float* upd_b   = (const float*)d_in[9];
    const float* ln_g    = (const float*)d_in[10];
    const float* ln_b    = (const float*)d_in[11];
    const float* aq_w    = (const float*)d_in[12];
    const float* aq_b    = (const float*)d_in[13];
    const float* pp_w    = (const float*)d_in[14];
    const float* pp_b    = (const float*)d_in[15];
    const float* v1_w    = (const float*)d_in[16];
    const float* v1_b    = (const float*)d_in[17];
    const float* v2_w    = (const float*)d_in[18];
    const float* v2_b    = (const float*)d_in[19];
    const float* tf_w    = (const float*)d_in[20];
    const float* tf_b    = (const float*)d_in[21];

    int B = in_sizes[0] / (CHN * NN);
    size_t smem = sizeof(Smem);
    cudaFuncSetAttribute(hexgnn_kernel, cudaFuncAttributeMaxDynamicSharedMemorySize,
                         (int)smem);
    hexgnn_kernel<<<B, NT, smem>>>(x, in_w, in_b, in_g, in_beta, msg_w, upd_w,
                                   upd_b, ln_g, ln_b, aq_w, aq_b, pp_w, pp_b,
                                   v1_w, v1_b, v2_w, v2_b, tf_w, tf_b,
                                   (float*)d_out, B);
}